// round 6
// baseline (speedup 1.0000x reference)
#include <cuda_runtime.h>

// Signature kernel (Goursat PDE) for 16x16 pairs of length-128, dim-8 paths.
// 2 pairs per CTA (256 threads). Phase 1: RBF Gram + fused finite-diff into
// SMEM, each 128-thread half handles one pair. Phase 2: anti-diagonal
// wavefront entirely inside ONE WARP per pair (8 grid rows per thread,
// state in registers, one shfl per diagonal, ZERO barriers).

#define LPATH 128
#define DIMS  8
#define DN    127   // diff rows/cols
#define DSTR  128   // diff row stride (floats)
#define MROW  254   // PDE grid M = N = (LPATH-1)*2

// SMEM layout (floats)
#define SM_SX   0                    // sx   [1024]
#define SM_SY   1024                 // sy   [2][1024]
#define SM_XN   3072                 // xn   [128]
#define SM_YN   3200                 // yn   [2][128]
#define SM_KB   3456                 // kb   [2][8*128]  (ring of K rows)
#define SM_DIFF 5504                 // diff [2][127*128]
#define SMEM_FLOATS (5504 + 2 * (DN * DSTR))   // 38016 floats = 152064 B

extern __shared__ float smem[];

// One wavefront sub-step at diagonal d. Rows with (k parity != d parity)
// have odd j = d - row there and load a fresh inc (reused next sub-step).
#define SUBSTEP(DVAL, LOADKPAR)                                              \
    do {                                                                     \
        const int d_ = (DVAL);                                               \
        float nbc = __shfl_up_sync(0xffffffffu, cur[7], 1);                  \
        if (lane == 0) nbc = 1.f;                                            \
        const int dml = d_ - (lane << 3) - 1;  /* j_k - 1 = dml - k */       \
        _Pragma("unroll")                                                    \
        for (int k = 7; k >= 0; k--) {                                       \
            if ((k & 1) == (LOADKPAR)) {                                     \
                unsigned cc = (unsigned)(dml - k) >> 1;                      \
                bool ok = (cc <= 126u);                                      \
                if (k == 0) ok = ok && (lane != 0);    /* row 0 inert   */   \
                if (k == 7) ok = ok && (lane != 31);   /* row 255 inert */   \
                if (ok) {                                                    \
                    float inc = diffw[roff[k] + (int)cc];                    \
                    float i2  = inc * inc * (1.f / 12.f);                    \
                    c1[k] = fmaf(0.5f, inc, 1.f + i2);                       \
                    c2[k] = 1.f - i2;                                        \
                }                                                            \
            }                                                                \
            float k10 = (k == 0) ? nbc : cur[k - 1]; /* old: descending */   \
            float k00 = l10[k];                                              \
            l10[k] = k10;                                                    \
            cur[k] = (k10 + cur[k]) * c1[k] - k00 * c2[k];                   \
        }                                                                    \
    } while (0)

__global__ void __launch_bounds__(256, 1)
sig_pde_kernel(const float* __restrict__ xs, const float* __restrict__ ys,
               float* __restrict__ out, int By)
{
    const int t   = threadIdx.x;
    const int h   = t >> 7;     // which pair this half handles
    const int c   = t & 127;
    const int bx  = blockIdx.y;
    const int byp = blockIdx.x; // pair of y indices: 2*byp + h

    float* sx   = smem + SM_SX;
    float* sy   = smem + SM_SY + h * 1024;
    float* xn   = smem + SM_XN;
    float* yn   = smem + SM_YN + h * 128;
    float* kb   = smem + SM_KB + h * 1024;       // 8-slot row ring
    float* diff = smem + SM_DIFF + h * (DN * DSTR);

    // ---- load paths ----
    const float* gx = xs + (size_t)bx * (LPATH * DIMS);
    const float* gy = ys + (size_t)(2 * byp + h) * (LPATH * DIMS);
    #pragma unroll
    for (int i = c; i < LPATH * DIMS; i += 128) {
        if (h == 0) sx[i] = gx[i];
        sy[i] = gy[i];
    }
    __syncthreads();

    // ---- squared norms + y column in registers ----
    float yreg[DIMS];
    float ynorm = 0.f;
    #pragma unroll
    for (int k = 0; k < DIMS; k++) {
        float v = sy[c * DIMS + k];
        yreg[k] = v;
        ynorm = fmaf(v, v, ynorm);
    }
    yn[c] = ynorm;
    if (h == 0) {
        float s = 0.f;
        #pragma unroll
        for (int k = 0; k < DIMS; k++) { float v = sx[c * DIMS + k]; s = fmaf(v, v, s); }
        xn[c] = s;
    }
    __syncthreads();

    // ---- Phase 1: K rows (1/iter per half) + fused finite diff ----
    // exp(-sq/2) = exp2(sq * EXC)
    const float EXC = -0.72134752044448170367996234050095f;

    for (int i = 0; i < LPATH; i++) {
        float dot = 0.f;
        #pragma unroll
        for (int k = 0; k < DIMS; k++) dot = fmaf(sx[i * DIMS + k], yreg[k], dot);
        float sq = xn[i] + ynorm - 2.f * dot;
        kb[(i & 7) * 128 + c] = exp2f(sq * EXC);
        __syncthreads();
        if (i >= 1 && c < DN) {
            float k11v = kb[( i      & 7) * 128 + c + 1];
            float k00v = kb[((i - 1) & 7) * 128 + c    ];
            float k10v = kb[( i      & 7) * 128 + c    ];
            float k01v = kb[((i - 1) & 7) * 128 + c + 1];
            diff[(i - 1) * DSTR + c] = 0.25f * ((k11v + k00v) - (k10v + k01v));
        }
        // single barrier per row: 8-slot ring tolerates the 1-iter skew
    }
    __syncthreads();

    // ---- Phase 2: wavefront, one warp per pair, zero barriers ----
    const int wid = t >> 5;
    if (wid >= 2) return;                 // warps 2..7 done
    const int lane = t & 31;
    const float* diffw = smem + SM_DIFF + wid * (DN * DSTR);

    // thread owns grid rows 8*lane .. 8*lane+7
    float cur[8], l10[8], c1[8], c2[8];
    int roff[8];
    #pragma unroll
    for (int k = 0; k < 8; k++) {
        cur[k] = 1.f; l10[k] = 1.f; c1[k] = 1.f; c2[k] = 1.f;
        int row = 8 * lane + k;
        int r = (row - 1) >> 1;
        if (r < 0) r = 0;
        roff[k] = r * DSTR;
    }

    // d = 2 (even): odd-k rows have odd j and load
    SUBSTEP(2, 1);
    int d = 3;
    #pragma unroll 1
    for (int p = 0; p < 253; p++, d += 2) {
        SUBSTEP(d, 0);       // odd d: even-k rows load
        SUBSTEP(d + 1, 1);   // even d: odd-k rows load
    }
    // 1 + 506 = 507 diagonals: d = 2 .. 508

    // K[254, 254]: row 254 = 8*31 + 6 -> lane 31, k = 6
    if (lane == 31)
        out[bx * By + 2 * byp + wid] = cur[6];
}

extern "C" void kernel_launch(void* const* d_in, const int* in_sizes, int n_in,
                              void* d_out, int out_size)
{
    const float* xs = (const float*)d_in[0];
    const float* ys = (const float*)d_in[1];
    float* out = (float*)d_out;

    int Bx = in_sizes[0] / (LPATH * DIMS);
    int By = in_sizes[1] / (LPATH * DIMS);

    size_t shbytes = SMEM_FLOATS * sizeof(float);
    cudaFuncSetAttribute(sig_pde_kernel,
                         cudaFuncAttributeMaxDynamicSharedMemorySize,
                         (int)shbytes);

    dim3 grid(By / 2, Bx);
    sig_pde_kernel<<<grid, 256, shbytes>>>(xs, ys, out, By);
}